// round 1
// baseline (speedup 1.0000x reference)
#include <cuda_runtime.h>
#include <math.h>

#define H 1024
#define L 4096
#define V 50257
#define G3 3072
#define X2 2048

// ---------------- scratch (device globals, no allocation) ----------------
__device__ float g_qwp[8 * H];        // qW partials (8 i-chunks)
__device__ float g_qW[H];             // query @ Wq
__device__ float g_scorep[L * 8];     // per-col-block partial scores
__device__ float g_attn[L];           // softmax(scores)
__device__ float g_ctxp[8 * H];       // context partials (8 l-chunks)
__device__ float g_x[X2];             // concat(context, relu(emb))
__device__ float g_gi[G3];            // GRU input gates
__device__ float g_gh[G3];            // GRU hidden gates
__device__ float g_h0n[H];            // layer-0 new hidden
__device__ float g_h1n[H];            // layer-1 new hidden
__device__ float g_mpart[256];        // logsumexp partial max
__device__ float g_spart[256];        // logsumexp partial sum
__device__ float g_lse;               // final logsumexp

__device__ __forceinline__ float sigmoidf_(float x) { return 1.0f / (1.0f + expf(-x)); }

// ---------------- K1: qW partials.  qW[j] = sum_i q[i]*Wq[i*H+j] ----------------
// grid (4 jblocks, 8 iblocks), 256 threads
__global__ void k_qw_partial(const float* __restrict__ hidden, const float* __restrict__ Wq) {
    int j  = blockIdx.x * 256 + threadIdx.x;
    int ib = blockIdx.y;
    const float* q = hidden + H;  // last layer hidden = query
    float acc = 0.f;
    int i0 = ib * 128;
#pragma unroll 4
    for (int i = i0; i < i0 + 128; i++)
        acc += q[i] * Wq[i * H + j];
    g_qwp[ib * H + j] = acc;
}

// ---------------- K2: qW reduce ----------------
__global__ void k_qw_reduce() {
    int j = blockIdx.x * 256 + threadIdx.x;
    float s = 0.f;
#pragma unroll
    for (int p = 0; p < 8; p++) s += g_qwp[p * H + j];
    g_qW[j] = s;
}

// ---------------- K3: attention GEMM + tanh + wv dot (partial per col-block) ----
// C = enc[L,H] @ Wk[H,H]; scorep[l][bn] = sum_{j in bn-chunk} tanh(C[l,j]+qW[j])*wv[j]
// BM=128, BN=128, BK=8; grid (8 bn, 32 bm), 256 threads
__global__ void k_attn_gemm(const float* __restrict__ enc, const float* __restrict__ Wk,
                            const float* __restrict__ wv) {
    __shared__ float As[8][128];
    __shared__ float Bs[8][128];
    __shared__ float red[128][17];

    const int bn = blockIdx.x, bm = blockIdx.y;
    const int tid = threadIdx.x;
    const int tx = tid & 15, ty = tid >> 4;

    float acc[8][8];
#pragma unroll
    for (int i = 0; i < 8; i++)
#pragma unroll
        for (int j = 0; j < 8; j++) acc[i][j] = 0.f;

    const int rowA = tid >> 1;            // 0..127
    const int ka   = (tid & 1) * 4;       // 0 or 4
    const int kb   = tid >> 5;            // 0..7
    const int colB = (tid & 31) * 4;      // 0..124

    const float* encBase = enc + ((size_t)(bm * 128 + rowA)) * H + ka;
    const float* wkBase  = Wk + (size_t)kb * H + bn * 128 + colB;

    for (int k0 = 0; k0 < H; k0 += 8) {
        float4 a = *(const float4*)(encBase + k0);
        As[ka + 0][rowA] = a.x;
        As[ka + 1][rowA] = a.y;
        As[ka + 2][rowA] = a.z;
        As[ka + 3][rowA] = a.w;
        float4 b = *(const float4*)(wkBase + (size_t)k0 * H);
        *(float4*)&Bs[kb][colB] = b;
        __syncthreads();
#pragma unroll
        for (int kk = 0; kk < 8; kk++) {
            float ar[8], br[8];
            float4 a0 = *(float4*)&As[kk][ty * 8];
            float4 a1 = *(float4*)&As[kk][ty * 8 + 4];
            float4 b0 = *(float4*)&Bs[kk][tx * 8];
            float4 b1 = *(float4*)&Bs[kk][tx * 8 + 4];
            ar[0] = a0.x; ar[1] = a0.y; ar[2] = a0.z; ar[3] = a0.w;
            ar[4] = a1.x; ar[5] = a1.y; ar[6] = a1.z; ar[7] = a1.w;
            br[0] = b0.x; br[1] = b0.y; br[2] = b0.z; br[3] = b0.w;
            br[4] = b1.x; br[5] = b1.y; br[6] = b1.z; br[7] = b1.w;
#pragma unroll
            for (int i = 0; i < 8; i++)
#pragma unroll
                for (int j = 0; j < 8; j++) acc[i][j] += ar[i] * br[j];
        }
        __syncthreads();
    }

    // epilogue: tanh(acc + qW) * wv, partial sum over this block's 8 cols
    float part[8];
#pragma unroll
    for (int i = 0; i < 8; i++) {
        float s = 0.f;
#pragma unroll
        for (int j = 0; j < 8; j++) {
            int col = bn * 128 + tx * 8 + j;
            s += tanhf(acc[i][j] + g_qW[col]) * wv[col];
        }
        part[i] = s;
    }
#pragma unroll
    for (int i = 0; i < 8; i++) red[ty * 8 + i][tx] = part[i];
    __syncthreads();
    if (tid < 128) {
        float s = 0.f;
#pragma unroll
        for (int p = 0; p < 16; p++) s += red[tid][p];
        g_scorep[(size_t)(bm * 128 + tid) * 8 + bn] = s;
    }
}

// ---------------- K4: softmax over L=4096 (single block, 1024 threads) ----------
__global__ void k_attn_softmax() {
    __shared__ float sred[1024];
    int tid = threadIdx.x;
    float v[4];
    float mx = -INFINITY;
#pragma unroll
    for (int t = 0; t < 4; t++) {
        int l = tid * 4 + t;
        float s = 0.f;
#pragma unroll
        for (int p = 0; p < 8; p++) s += g_scorep[(size_t)l * 8 + p];
        v[t] = s;
        mx = fmaxf(mx, s);
    }
    sred[tid] = mx;
    __syncthreads();
    for (int o = 512; o > 0; o >>= 1) {
        if (tid < o) sred[tid] = fmaxf(sred[tid], sred[tid + o]);
        __syncthreads();
    }
    float M = sred[0];
    __syncthreads();
    float e[4], s = 0.f;
#pragma unroll
    for (int t = 0; t < 4; t++) { e[t] = expf(v[t] - M); s += e[t]; }
    sred[tid] = s;
    __syncthreads();
    for (int o = 512; o > 0; o >>= 1) {
        if (tid < o) sred[tid] += sred[tid + o];
        __syncthreads();
    }
    float inv = 1.0f / sred[0];
#pragma unroll
    for (int t = 0; t < 4; t++) g_attn[tid * 4 + t] = e[t] * inv;
}

// ---------------- K5: context partials.  ctx[j] = sum_l attn[l]*enc[l,j] --------
// grid (8 jchunks, 8 lchunks), 128 threads
__global__ void k_ctx_partial(const float* __restrict__ enc) {
    int j  = blockIdx.x * 128 + threadIdx.x;
    int lc = blockIdx.y;
    float acc = 0.f;
    int l0 = lc * 512;
#pragma unroll 4
    for (int l = l0; l < l0 + 512; l++)
        acc += g_attn[l] * enc[(size_t)l * H + j];
    g_ctxp[lc * H + j] = acc;
}

// ---------------- K6: build x = concat(context, relu(emb[token])) --------------
// grid 8, 256 threads
__global__ void k_build_x(const int* __restrict__ input, const float* __restrict__ emb) {
    int idx = blockIdx.x * 256 + threadIdx.x;
    if (idx < H) {
        float s = 0.f;
#pragma unroll
        for (int p = 0; p < 8; p++) s += g_ctxp[p * H + idx];
        g_x[idx] = s;
    } else {
        int tok = input[0];
        float e = emb[(size_t)tok * H + (idx - H)];
        g_x[idx] = fmaxf(e, 0.f);
    }
}

// ---------------- K7: GRU GEMVs (gi = Wi@x + bi ; gh = Wh@h + bh) ---------------
// one warp per output row; 6144 warps -> 768 blocks x 256 threads
__global__ void k_gru_gemv(const float* __restrict__ Wi, const float* __restrict__ Wh,
                           const float* __restrict__ bi, const float* __restrict__ bh,
                           const float* __restrict__ x, int xlen,
                           const float* __restrict__ h) {
    __shared__ float sxh[X2 + H];
    int tid = threadIdx.x;
    for (int i = tid; i < xlen; i += 256) sxh[i] = x[i];
    for (int i = tid; i < H; i += 256) sxh[X2 + i] = h[i];
    __syncthreads();

    int warp = blockIdx.x * 8 + (tid >> 5);
    int lane = tid & 31;
    if (warp < G3) {
        const float* W = Wi + (size_t)warp * xlen;
        float acc = 0.f;
        for (int c = lane * 4; c < xlen; c += 128) {
            float4 w = *(const float4*)(W + c);
            acc += w.x * sxh[c] + w.y * sxh[c + 1] + w.z * sxh[c + 2] + w.w * sxh[c + 3];
        }
#pragma unroll
        for (int o = 16; o > 0; o >>= 1) acc += __shfl_down_sync(0xffffffffu, acc, o);
        if (lane == 0) g_gi[warp] = acc + bi[warp];
    } else {
        int r = warp - G3;
        const float* W = Wh + (size_t)r * H;
        float acc = 0.f;
        for (int c = lane * 4; c < H; c += 128) {
            float4 w = *(const float4*)(W + c);
            acc += w.x * sxh[X2 + c] + w.y * sxh[X2 + c + 1] + w.z * sxh[X2 + c + 2] + w.w * sxh[X2 + c + 3];
        }
#pragma unroll
        for (int o = 16; o > 0; o >>= 1) acc += __shfl_down_sync(0xffffffffu, acc, o);
        if (lane == 0) g_gh[r] = acc + bh[r];
    }
}

// ---------------- K8: GRU elementwise combine ----------------
// grid 4 x 256
__global__ void k_gru_combine(const float* __restrict__ h_prev,
                              float* __restrict__ h_scratch,
                              float* __restrict__ out_hidden) {
    int k = blockIdx.x * 256 + threadIdx.x;
    float r = sigmoidf_(g_gi[k] + g_gh[k]);
    float z = sigmoidf_(g_gi[k + H] + g_gh[k + H]);
    float n = tanhf(g_gi[k + 2 * H] + r * g_gh[k + 2 * H]);
    float hp = h_prev[k];
    float hn = (1.0f - z) * n + z * hp;
    h_scratch[k] = hn;
    out_hidden[k] = hn;
}

// ---------------- K11: logits GEMV + per-block softmax stats --------------------
// grid 197 x 256 ; logits[v] = sum_h h1n[h]*Wd[h*V+v] + bd[v]
__global__ void k_logits(const float* __restrict__ Wd, const float* __restrict__ bd,
                         float* __restrict__ out) {
    __shared__ float sh[H];
    __shared__ float sred[256];
    int tid = threadIdx.x;
    for (int i = tid; i < H; i += 256) sh[i] = g_h1n[i];
    __syncthreads();

    int v = blockIdx.x * 256 + tid;
    float acc = -INFINITY;
    if (v < V) {
        acc = bd[v];
#pragma unroll 8
        for (int h = 0; h < H; h++)
            acc += sh[h] * Wd[(size_t)h * V + v];
        out[v] = acc;
    }
    // block max
    sred[tid] = acc;
    __syncthreads();
    for (int o = 128; o > 0; o >>= 1) {
        if (tid < o) sred[tid] = fmaxf(sred[tid], sred[tid + o]);
        __syncthreads();
    }
    float bm = sred[0];
    __syncthreads();
    // block sum of exp
    sred[tid] = (v < V) ? expf(acc - bm) : 0.f;
    __syncthreads();
    for (int o = 128; o > 0; o >>= 1) {
        if (tid < o) sred[tid] += sred[tid + o];
        __syncthreads();
    }
    if (tid == 0) {
        g_mpart[blockIdx.x] = bm;
        g_spart[blockIdx.x] = sred[0];
    }
}

// ---------------- K12: combine logsumexp partials (1 block, 256 threads) --------
__global__ void k_lse_combine(int nparts) {
    __shared__ float sm[256];
    __shared__ float ss[256];
    int t = threadIdx.x;
    float m = (t < nparts) ? g_mpart[t] : -INFINITY;
    sm[t] = m;
    __syncthreads();
    for (int o = 128; o > 0; o >>= 1) {
        if (t < o) sm[t] = fmaxf(sm[t], sm[t + o]);
        __syncthreads();
    }
    float M = sm[0];
    float s = (t < nparts) ? g_spart[t] * expf(g_mpart[t] - M) : 0.f;
    ss[t] = s;
    __syncthreads();
    for (int o = 128; o > 0; o >>= 1) {
        if (t < o) ss[t] += ss[t + o];
        __syncthreads();
    }
    if (t == 0) g_lse = M + logf(ss[0]);
}

// ---------------- K13: final log-softmax subtract ----------------
__global__ void k_logp_final(float* __restrict__ out) {
    int v = blockIdx.x * 256 + threadIdx.x;
    if (v < V) out[v] = out[v] - g_lse;
}

// ---------------- launcher ----------------
extern "C" void kernel_launch(void* const* d_in, const int* in_sizes, int n_in,
                              void* d_out, int out_size) {
    const int*   input  = (const int*)d_in[0];
    const float* hidden = (const float*)d_in[1];
    const float* enc    = (const float*)d_in[2];
    const float* emb    = (const float*)d_in[3];
    const float* Wq     = (const float*)d_in[4];
    const float* Wk     = (const float*)d_in[5];
    const float* wv     = (const float*)d_in[6];
    const float* W_ih0  = (const float*)d_in[7];
    const float* W_hh0  = (const float*)d_in[8];
    const float* b_ih0  = (const float*)d_in[9];
    const float* b_hh0  = (const float*)d_in[10];
    const float* W_ih1  = (const float*)d_in[11];
    const float* W_hh1  = (const float*)d_in[12];
    const float* b_ih1  = (const float*)d_in[13];
    const float* b_hh1  = (const float*)d_in[14];
    const float* Wd     = (const float*)d_in[15];
    const float* bd     = (const float*)d_in[16];

    float* out = (float*)d_out;  // [0,V) logp ; [V, V+2048) new hidden

    float* g_h0n_p; cudaGetSymbolAddress((void**)&g_h0n_p, g_h0n);
    float* g_h1n_p; cudaGetSymbolAddress((void**)&g_h1n_p, g_h1n);
    float* g_x_p;   cudaGetSymbolAddress((void**)&g_x_p, g_x);

    // 1-2: qW = query @ Wq
    k_qw_partial<<<dim3(4, 8), 256>>>(hidden, Wq);
    k_qw_reduce<<<4, 256>>>();
    // 3: scores GEMM (enc @ Wk, tanh, dot wv) -> partials
    k_attn_gemm<<<dim3(8, 32), 256>>>(enc, Wk, wv);
    // 4: softmax over L
    k_attn_softmax<<<1, 1024>>>();
    // 5-6: context = attn^T @ enc ; x = concat(context, relu(emb[token]))
    k_ctx_partial<<<dim3(8, 8), 128>>>(enc);
    k_build_x<<<8, 256>>>(input, emb);
    // 7-8: GRU layer 0 (x len 2048, h = hidden[0])
    k_gru_gemv<<<768, 256>>>(W_ih0, W_hh0, b_ih0, b_hh0, g_x_p, X2, hidden);
    k_gru_combine<<<4, 256>>>(hidden, g_h0n_p, out + V);
    // 9-10: GRU layer 1 (x = h0n len 1024, h = hidden[1])
    k_gru_gemv<<<768, 256>>>(W_ih1, W_hh1, b_ih1, b_hh1, g_h0n_p, H, hidden + H);
    k_gru_combine<<<4, 256>>>(hidden + H, g_h1n_p, out + V + H);
    // 11-13: logits GEMV + log_softmax
    const int nblk = (V + 255) / 256;  // 197
    k_logits<<<nblk, 256>>>(Wd, bd, out);
    k_lse_combine<<<1, 256>>>(nblk);
    k_logp_final<<<nblk, 256>>>(out);
}

// round 2
// speedup vs baseline: 1.4193x; 1.4193x over previous
#include <cuda_runtime.h>
#include <math.h>
#include <stdint.h>

#define H 1024
#define L 4096
#define V 50257
#define G3 3072
#define X2 2048

#define NPART 16   // score partials per row (8 n-blocks x 2 warpN)

// ---------------- scratch (device globals, no allocation) ----------------
__device__ float g_qwp[8 * H];        // qW partials (8 i-chunks)
__device__ float g_qW[H];             // query @ Wq
__device__ float g_scorep[NPART * L]; // transposed: [p][l] for coalesced reduce
__device__ float g_attn[L];           // softmax(scores)
__device__ float g_ctxp[8 * H];       // context partials (8 l-chunks)
__device__ float g_x[X2];             // concat(context, relu(emb))
__device__ float g_gi[G3];            // GRU input gates
__device__ float g_gh[G3];            // GRU hidden gates
__device__ float g_h0n[H];            // layer-0 new hidden
__device__ float g_h1n[H];            // layer-1 new hidden
__device__ float g_mpart[256];        // logsumexp partial max
__device__ float g_spart[256];        // logsumexp partial sum
__device__ float g_lse;               // final logsumexp

__device__ __forceinline__ float sigmoidf_(float x) { return 1.0f / (1.0f + expf(-x)); }

__device__ __forceinline__ uint32_t f2tf32(float x) {
    uint32_t r;
    asm("cvt.rna.tf32.f32 %0, %1;" : "=r"(r) : "f"(x));
    return r;
}

__device__ __forceinline__ void mma_tf32(float c[4], const uint32_t a[4],
                                         uint32_t b0, uint32_t b1) {
    asm volatile(
        "mma.sync.aligned.m16n8k8.row.col.f32.tf32.tf32.f32 "
        "{%0,%1,%2,%3}, {%4,%5,%6,%7}, {%8,%9}, {%0,%1,%2,%3};"
        : "+f"(c[0]), "+f"(c[1]), "+f"(c[2]), "+f"(c[3])
        : "r"(a[0]), "r"(a[1]), "r"(a[2]), "r"(a[3]), "r"(b0), "r"(b1));
}

// ---------------- K1: qW partials.  qW[j] = sum_i q[i]*Wq[i*H+j] ----------------
__global__ void k_qw_partial(const float* __restrict__ hidden, const float* __restrict__ Wq) {
    int j  = blockIdx.x * 256 + threadIdx.x;
    int ib = blockIdx.y;
    const float* q = hidden + H;  // last layer hidden = query
    float acc = 0.f;
    int i0 = ib * 128;
#pragma unroll 4
    for (int i = i0; i < i0 + 128; i++)
        acc += q[i] * Wq[i * H + j];
    g_qwp[ib * H + j] = acc;
}

__global__ void k_qw_reduce() {
    int j = blockIdx.x * 256 + threadIdx.x;
    float s = 0.f;
#pragma unroll
    for (int p = 0; p < 8; p++) s += g_qwp[p * H + j];
    g_qW[j] = s;
}

// ---------------- K3: attention GEMM on tensor cores (tf32 mma.sync) ------------
// C = enc[L,H] @ Wk[H,H]; scorep[p][l] = sum_{j in chunk} tanh(C[l,j]+qW[j])*wv[j]
// BM=128, BN=128, BK=16; 256 threads = 8 warps (4 m x 2 n), warp tile 32x64.
__global__ void k_attn_gemm_mma(const float* __restrict__ enc,
                                const float* __restrict__ Wk,
                                const float* __restrict__ wv) {
    __shared__ uint32_t As[128][20];   // [m][k] padded: bank-conflict-free frag loads
    __shared__ uint32_t Bs[16][132];   // [k][n] padded

    const int tid  = threadIdx.x;
    const int warp = tid >> 5, lane = tid & 31;
    const int wm = warp >> 1, wn = warp & 1;
    const int g = lane >> 2, t = lane & 3;
    const int bn = blockIdx.x, bm = blockIdx.y;

    float acc[2][8][4];
#pragma unroll
    for (int mt = 0; mt < 2; mt++)
#pragma unroll
        for (int nt = 0; nt < 8; nt++)
#pragma unroll
            for (int i = 0; i < 4; i++) acc[mt][nt][i] = 0.f;

    // A load mapping: 2 threads per row, 8 consecutive k each
    const int arow = tid >> 1;
    const int akh  = (tid & 1) * 8;
    const float* Ab = enc + (size_t)(bm * 128 + arow) * H + akh;
    // B load mapping: row pair (bkr, bkr+8), 4 consecutive cols
    const int bkr  = tid >> 5;
    const int bcol = lane * 4;
    const float* Bb = Wk + (size_t)bkr * H + bn * 128 + bcol;

    for (int k0 = 0; k0 < H; k0 += 16) {
        float4 av0 = *(const float4*)(Ab + k0);
        float4 av1 = *(const float4*)(Ab + k0 + 4);
        uint4 ap0 = make_uint4(f2tf32(av0.x), f2tf32(av0.y), f2tf32(av0.z), f2tf32(av0.w));
        uint4 ap1 = make_uint4(f2tf32(av1.x), f2tf32(av1.y), f2tf32(av1.z), f2tf32(av1.w));
        *(uint4*)&As[arow][akh]     = ap0;
        *(uint4*)&As[arow][akh + 4] = ap1;

        float4 bv0 = *(const float4*)(Bb + (size_t)k0 * H);
        float4 bv1 = *(const float4*)(Bb + (size_t)(k0 + 8) * H);
        uint4 bp0 = make_uint4(f2tf32(bv0.x), f2tf32(bv0.y), f2tf32(bv0.z), f2tf32(bv0.w));
        uint4 bp1 = make_uint4(f2tf32(bv1.x), f2tf32(bv1.y), f2tf32(bv1.z), f2tf32(bv1.w));
        *(uint4*)&Bs[bkr][bcol]     = bp0;
        *(uint4*)&Bs[bkr + 8][bcol] = bp1;
        __syncthreads();

#pragma unroll
        for (int ks = 0; ks < 2; ks++) {
            const int kk = ks * 8;
            uint32_t a[2][4];
#pragma unroll
            for (int mt = 0; mt < 2; mt++) {
                int r0 = wm * 32 + mt * 16 + g;
                a[mt][0] = As[r0][kk + t];
                a[mt][1] = As[r0 + 8][kk + t];
                a[mt][2] = As[r0][kk + t + 4];
                a[mt][3] = As[r0 + 8][kk + t + 4];
            }
#pragma unroll
            for (int nt = 0; nt < 8; nt++) {
                int c0 = wn * 64 + nt * 8 + g;
                uint32_t b0 = Bs[kk + t][c0];
                uint32_t b1 = Bs[kk + t + 4][c0];
                mma_tf32(acc[0][nt], a[0], b0, b1);
                mma_tf32(acc[1][nt], a[1], b0, b1);
            }
        }
        __syncthreads();
    }

    // epilogue: tanh(acc + qW) * wv, partial-sum over this warp's 64 cols
    float s[4] = {0.f, 0.f, 0.f, 0.f};  // rows: g, g+8 (mt0); 16+g, 24+g (mt1)
#pragma unroll
    for (int mt = 0; mt < 2; mt++) {
#pragma unroll
        for (int nt = 0; nt < 8; nt++) {
            int col = bn * 128 + wn * 64 + nt * 8 + 2 * t;
            float qw0 = g_qW[col], qw1 = g_qW[col + 1];
            float w0 = wv[col], w1 = wv[col + 1];
            s[mt * 2 + 0] += tanhf(acc[mt][nt][0] + qw0) * w0 + tanhf(acc[mt][nt][1] + qw1) * w1;
            s[mt * 2 + 1] += tanhf(acc[mt][nt][2] + qw0) * w0 + tanhf(acc[mt][nt][3] + qw1) * w1;
        }
    }
#pragma unroll
    for (int i = 0; i < 4; i++) {
        s[i] += __shfl_xor_sync(0xffffffffu, s[i], 1);
        s[i] += __shfl_xor_sync(0xffffffffu, s[i], 2);
    }
    if (t == 0) {
        int p = bn * 2 + wn;                 // 0..15
        int rowbase = bm * 128 + wm * 32;
        g_scorep[(size_t)p * L + rowbase + g]      = s[0];
        g_scorep[(size_t)p * L + rowbase + g + 8]  = s[1];
        g_scorep[(size_t)p * L + rowbase + g + 16] = s[2];
        g_scorep[(size_t)p * L + rowbase + g + 24] = s[3];
    }
}

// ---------------- K4: softmax over L=4096 (single block, 1024 threads) ----------
__global__ void k_attn_softmax() {
    __shared__ float sred[32];
    int tid = threadIdx.x;
    int wid = tid >> 5, lane = tid & 31;
    float v[4];
    float mx = -INFINITY;
#pragma unroll
    for (int tt = 0; tt < 4; tt++) {
        int l = tt * 1024 + tid;
        float s = 0.f;
#pragma unroll
        for (int p = 0; p < NPART; p++) s += g_scorep[(size_t)p * L + l];
        v[tt] = s;
        mx = fmaxf(mx, s);
    }
#pragma unroll
    for (int o = 16; o > 0; o >>= 1) mx = fmaxf(mx, __shfl_xor_sync(0xffffffffu, mx, o));
    if (lane == 0) sred[wid] = mx;
    __syncthreads();
    if (wid == 0) {
        float m = sred[lane];
#pragma unroll
        for (int o = 16; o > 0; o >>= 1) m = fmaxf(m, __shfl_xor_sync(0xffffffffu, m, o));
        sred[lane] = m;
    }
    __syncthreads();
    float M = sred[0];
    float e[4], s = 0.f;
#pragma unroll
    for (int tt = 0; tt < 4; tt++) { e[tt] = expf(v[tt] - M); s += e[tt]; }
#pragma unroll
    for (int o = 16; o > 0; o >>= 1) s += __shfl_xor_sync(0xffffffffu, s, o);
    __syncthreads();
    if (lane == 0) sred[wid] = s;
    __syncthreads();
    if (wid == 0) {
        float q = sred[lane];
#pragma unroll
        for (int o = 16; o > 0; o >>= 1) q += __shfl_xor_sync(0xffffffffu, q, o);
        sred[lane] = q;
    }
    __syncthreads();
    float inv = 1.0f / sred[0];
#pragma unroll
    for (int tt = 0; tt < 4; tt++) g_attn[tt * 1024 + tid] = e[tt] * inv;
}

// ---------------- K5: context partials.  ctx[j] = sum_l attn[l]*enc[l,j] --------
__global__ void k_ctx_partial(const float* __restrict__ enc) {
    int j  = blockIdx.x * 128 + threadIdx.x;
    int lc = blockIdx.y;
    float acc = 0.f;
    int l0 = lc * 512;
#pragma unroll 4
    for (int l = l0; l < l0 + 512; l++)
        acc += g_attn[l] * enc[(size_t)l * H + j];
    g_ctxp[lc * H + j] = acc;
}

// ---------------- K6: build x = concat(context, relu(emb[token])) --------------
__global__ void k_build_x(const int* __restrict__ input, const float* __restrict__ emb) {
    int idx = blockIdx.x * 256 + threadIdx.x;
    if (idx < H) {
        float s = 0.f;
#pragma unroll
        for (int p = 0; p < 8; p++) s += g_ctxp[p * H + idx];
        g_x[idx] = s;
    } else {
        int tok = input[0];
        float e = emb[(size_t)tok * H + (idx - H)];
        g_x[idx] = fmaxf(e, 0.f);
    }
}

// ---------------- K7: GRU GEMVs ----------------
__global__ void k_gru_gemv(const float* __restrict__ Wi, const float* __restrict__ Wh,
                           const float* __restrict__ bi, const float* __restrict__ bh,
                           const float* __restrict__ x, int xlen,
                           const float* __restrict__ h) {
    __shared__ float sxh[X2 + H];
    int tid = threadIdx.x;
    for (int i = tid; i < xlen; i += 256) sxh[i] = x[i];
    for (int i = tid; i < H; i += 256) sxh[X2 + i] = h[i];
    __syncthreads();

    int warp = blockIdx.x * 8 + (tid >> 5);
    int lane = tid & 31;
    if (warp < G3) {
        const float* W = Wi + (size_t)warp * xlen;
        float acc = 0.f;
        for (int c = lane * 4; c < xlen; c += 128) {
            float4 w = *(const float4*)(W + c);
            acc += w.x * sxh[c] + w.y * sxh[c + 1] + w.z * sxh[c + 2] + w.w * sxh[c + 3];
        }
#pragma unroll
        for (int o = 16; o > 0; o >>= 1) acc += __shfl_down_sync(0xffffffffu, acc, o);
        if (lane == 0) g_gi[warp] = acc + bi[warp];
    } else {
        int r = warp - G3;
        const float* W = Wh + (size_t)r * H;
        float acc = 0.f;
        for (int c = lane * 4; c < H; c += 128) {
            float4 w = *(const float4*)(W + c);
            acc += w.x * sxh[X2 + c] + w.y * sxh[X2 + c + 1] + w.z * sxh[X2 + c + 2] + w.w * sxh[X2 + c + 3];
        }
#pragma unroll
        for (int o = 16; o > 0; o >>= 1) acc += __shfl_down_sync(0xffffffffu, acc, o);
        if (lane == 0) g_gh[r] = acc + bh[r];
    }
}

// ---------------- K8: GRU elementwise combine ----------------
__global__ void k_gru_combine(const float* __restrict__ h_prev,
                              float* __restrict__ h_scratch,
                              float* __restrict__ out_hidden) {
    int k = blockIdx.x * 256 + threadIdx.x;
    float r = sigmoidf_(g_gi[k] + g_gh[k]);
    float z = sigmoidf_(g_gi[k + H] + g_gh[k + H]);
    float n = tanhf(g_gi[k + 2 * H] + r * g_gh[k + 2 * H]);
    float hp = h_prev[k];
    float hn = (1.0f - z) * n + z * hp;
    h_scratch[k] = hn;
    out_hidden[k] = hn;
}

// ---------------- K11: logits GEMV + per-block softmax stats --------------------
__global__ void k_logits(const float* __restrict__ Wd, const float* __restrict__ bd,
                         float* __restrict__ out) {
    __shared__ float sh[H];
    __shared__ float sred[256];
    int tid = threadIdx.x;
    for (int i = tid; i < H; i += 256) sh[i] = g_h1n[i];
    __syncthreads();

    int v = blockIdx.x * 256 + tid;
    float acc = -INFINITY;
    if (v < V) {
        acc = bd[v];
#pragma unroll 8
        for (int h = 0; h < H; h++)
            acc += sh[h] * Wd[(size_t)h * V + v];
        out[v] = acc;
    }
    sred[tid] = acc;
    __syncthreads();
    for (int o = 128; o > 0; o >>= 1) {
        if (tid < o) sred[tid] = fmaxf(sred[tid], sred[tid + o]);
        __syncthreads();
    }
    float bm = sred[0];
    __syncthreads();
    sred[tid] = (v < V) ? expf(acc - bm) : 0.f;
    __syncthreads();
    for (int o = 128; o > 0; o >>= 1) {
        if (tid < o) sred[tid] += sred[tid + o];
        __syncthreads();
    }
    if (tid == 0) {
        g_mpart[blockIdx.x] = bm;
        g_spart[blockIdx.x] = sred[0];
    }
}

__global__ void k_lse_combine(int nparts) {
    __shared__ float sm[256];
    __shared__ float ss[256];
    int t = threadIdx.x;
    float m = (t < nparts) ? g_mpart[t] : -INFINITY;
    sm[t] = m;
    __syncthreads();
    for (int o = 128; o > 0; o >>= 1) {
        if (t < o) sm[t] = fmaxf(sm[t], sm[t + o]);
        __syncthreads();
    }
    float M = sm[0];
    float s = (t < nparts) ? g_spart[t] * expf(g_mpart[t] - M) : 0.f;
    ss[t] = s;
    __syncthreads();
    for (int o = 128; o > 0; o >>= 1) {
        if (t < o) ss[t] += ss[t + o];
        __syncthreads();
    }
    if (t == 0) g_lse = M + logf(ss[0]);
}

__global__ void k_logp_final(float* __restrict__ out) {
    int v = blockIdx.x * 256 + threadIdx.x;
    if (v < V) out[v] = out[v] - g_lse;
}

// ---------------- launcher ----------------
extern "C" void kernel_launch(void* const* d_in, const int* in_sizes, int n_in,
                              void* d_out, int out_size) {
    const int*   input  = (const int*)d_in[0];
    const float* hidden = (const float*)d_in[1];
    const float* enc    = (const float*)d_in[2];
    const float* emb    = (const float*)d_in[3];
    const float* Wq     = (const float*)d_in[4];
    const float* Wk     = (const float*)d_in[5];
    const float* wv     = (const float*)d_in[6];
    const float* W_ih0  = (const float*)d_in[7];
    const float* W_hh0  = (const float*)d_in[8];
    const float* b_ih0  = (const float*)d_in[9];
    const float* b_hh0  = (const float*)d_in[10];
    const float* W_ih1  = (const float*)d_in[11];
    const float* W_hh1  = (const float*)d_in[12];
    const float* b_ih1  = (const float*)d_in[13];
    const float* b_hh1  = (const float*)d_in[14];
    const float* Wd     = (const float*)d_in[15];
    const float* bd     = (const float*)d_in[16];

    float* out = (float*)d_out;  // [0,V) logp ; [V, V+2048) new hidden

    float* g_h0n_p; cudaGetSymbolAddress((void**)&g_h0n_p, g_h0n);
    float* g_h1n_p; cudaGetSymbolAddress((void**)&g_h1n_p, g_h1n);
    float* g_x_p;   cudaGetSymbolAddress((void**)&g_x_p, g_x);

    k_qw_partial<<<dim3(4, 8), 256>>>(hidden, Wq);
    k_qw_reduce<<<4, 256>>>();
    k_attn_gemm_mma<<<dim3(8, 32), 256>>>(enc, Wk, wv);
    k_attn_softmax<<<1, 1024>>>();
    k_ctx_partial<<<dim3(8, 8), 128>>>(enc);
    k_build_x<<<8, 256>>>(input, emb);
    k_gru_gemv<<<768, 256>>>(W_ih0, W_hh0, b_ih0, b_hh0, g_x_p, X2, hidden);
    k_gru_combine<<<4, 256>>>(hidden, g_h0n_p, out + V);
    k_gru_gemv<<<768, 256>>>(W_ih1, W_hh1, b_ih1, b_hh1, g_h0n_p, H, hidden + H);
    k_gru_combine<<<4, 256>>>(hidden + H, g_h1n_p, out + V + H);
    const int nblk = (V + 255) / 256;  // 197
    k_logits<<<nblk, 256>>>(Wd, bd, out);
    k_lse_combine<<<1, 256>>>(nblk);
    k_logp_final<<<nblk, 256>>>(out);
}

// round 3
// speedup vs baseline: 2.3118x; 1.6289x over previous
#include <cuda_runtime.h>
#include <math.h>
#include <stdint.h>

#define H 1024
#define L 4096
#define V 50257
#define G3 3072
#define X2 2048

#define NPART 32   // score partials per row (8 bn-blocks x 4 warpN)

// ---------------- scratch (device globals, no allocation) ----------------
__device__ float g_qwp[32 * H];       // qW partials (32 i-chunks)
__device__ float g_qW[H];             // query @ Wq
__device__ float g_scorep[NPART * L]; // [p][l] transposed partials
__device__ float g_scores[L];         // reduced scores
__device__ float g_attn[L];           // UNNORMALIZED exp(s - max)
__device__ float g_invS;              // 1/sum(exp)
__device__ float g_gmax;              // global score max
__device__ float g_ctxp[32 * H];      // context partials (32 l-chunks)
__device__ float g_x[X2];             // concat(context, relu(emb))
__device__ float g_gi[G3];            // GRU input gates
__device__ float g_gh[G3];            // GRU hidden gates
__device__ float g_h0n[H];            // layer-0 new hidden
__device__ float g_h1n[H];            // layer-1 new hidden
__device__ float g_mpart[256];        // partial max
__device__ float g_spart[256];        // partial sum
__device__ float g_lse;               // final logsumexp

__device__ __forceinline__ float sigmoidf_(float x) { return 1.0f / (1.0f + expf(-x)); }

__device__ __forceinline__ uint32_t f2tf32(float x) {
    uint32_t r;
    asm("cvt.rna.tf32.f32 %0, %1;" : "=r"(r) : "f"(x));
    return r;
}

__device__ __forceinline__ void mma_tf32(float c[4], const uint32_t a[4],
                                         uint32_t b0, uint32_t b1) {
    asm volatile(
        "mma.sync.aligned.m16n8k8.row.col.f32.tf32.tf32.f32 "
        "{%0,%1,%2,%3}, {%4,%5,%6,%7}, {%8,%9}, {%0,%1,%2,%3};"
        : "+f"(c[0]), "+f"(c[1]), "+f"(c[2]), "+f"(c[3])
        : "r"(a[0]), "r"(a[1]), "r"(a[2]), "r"(a[3]), "r"(b0), "r"(b1));
}

// ---------------- K1: qW partials (grid 4 j x 32 i, 256 thr) ----------------
__global__ void k_qw_partial(const float* __restrict__ hidden, const float* __restrict__ Wq) {
    int j  = blockIdx.x * 256 + threadIdx.x;
    int i0 = blockIdx.y * 32;
    const float* q = hidden + H;  // last-layer hidden = query
    float acc = 0.f;
#pragma unroll
    for (int i = 0; i < 32; i++)
        acc += q[i0 + i] * Wq[(size_t)(i0 + i) * H + j];
    g_qwp[blockIdx.y * H + j] = acc;
}

__global__ void k_qw_reduce() {
    int j = blockIdx.x * 256 + threadIdx.x;
    float s = 0.f;
#pragma unroll
    for (int p = 0; p < 32; p++) s += g_qwp[p * H + j];
    g_qW[j] = s;
}

// ---------------- K3: attention GEMM, tf32 mma, pipelined --------------------
// BM=128, BN=128, BK=16; 8 warps as 2(m)x4(n); warp tile 64x32.
__global__ void __launch_bounds__(256, 2)
k_attn_gemm_mma(const float* __restrict__ enc, const float* __restrict__ Wk,
                const float* __restrict__ wv) {
    __shared__ uint32_t As[128][20];   // [m][k] pad 20: 20g+t conflict-free
    __shared__ uint32_t Bs[16][136];   // [k][n] pad 136: 8t+g conflict-free

    const int tid  = threadIdx.x;
    const int warp = tid >> 5, lane = tid & 31;
    const int wm = warp & 1, wn = warp >> 1;        // 2 m-warps x 4 n-warps
    const int g = lane >> 2, t = lane & 3;
    const int bn = blockIdx.x, bm = blockIdx.y;

    float acc[4][4][4];
#pragma unroll
    for (int mt = 0; mt < 4; mt++)
#pragma unroll
        for (int nt = 0; nt < 4; nt++)
#pragma unroll
            for (int i = 0; i < 4; i++) acc[mt][nt][i] = 0.f;

    // A: 128x16, 2 float4/thread. row = tid>>2 (+64), k = (tid&3)*4
    const int arow = tid >> 2;
    const int akc  = (tid & 3) * 4;
    const float* Ab = enc + (size_t)(bm * 128 + arow) * H + akc;
    // B: 16x128, 2 float4/thread. krow = tid>>5 (+8), n = (tid&31)*4
    const int bkr = tid >> 5;
    const int bnc = lane * 4;
    const float* Bb = Wk + (size_t)bkr * H + bn * 128 + bnc;

    float4 pa0, pa1, pb0, pb1;
    pa0 = *(const float4*)(Ab);
    pa1 = *(const float4*)(Ab + (size_t)64 * H);
    pb0 = *(const float4*)(Bb);
    pb1 = *(const float4*)(Bb + (size_t)8 * H);

    for (int it = 0; it < 64; ++it) {
        __syncthreads();
        *(uint4*)&As[arow][akc]      = make_uint4(f2tf32(pa0.x), f2tf32(pa0.y), f2tf32(pa0.z), f2tf32(pa0.w));
        *(uint4*)&As[arow + 64][akc] = make_uint4(f2tf32(pa1.x), f2tf32(pa1.y), f2tf32(pa1.z), f2tf32(pa1.w));
        *(uint4*)&Bs[bkr][bnc]       = make_uint4(f2tf32(pb0.x), f2tf32(pb0.y), f2tf32(pb0.z), f2tf32(pb0.w));
        *(uint4*)&Bs[bkr + 8][bnc]   = make_uint4(f2tf32(pb1.x), f2tf32(pb1.y), f2tf32(pb1.z), f2tf32(pb1.w));
        __syncthreads();

        if (it < 63) {
            size_t k0 = (size_t)(it + 1) * 16;
            pa0 = *(const float4*)(Ab + k0);
            pa1 = *(const float4*)(Ab + (size_t)64 * H + k0);
            pb0 = *(const float4*)(Bb + k0 * H);
            pb1 = *(const float4*)(Bb + (k0 + 8) * H);
        }

#pragma unroll
        for (int ks = 0; ks < 2; ks++) {
            const int kk = ks * 8;
            uint32_t a[4][4];
#pragma unroll
            for (int mt = 0; mt < 4; mt++) {
                int r0 = wm * 64 + mt * 16 + g;
                a[mt][0] = As[r0][kk + t];
                a[mt][1] = As[r0 + 8][kk + t];
                a[mt][2] = As[r0][kk + t + 4];
                a[mt][3] = As[r0 + 8][kk + t + 4];
            }
#pragma unroll
            for (int nt = 0; nt < 4; nt++) {
                int c0 = wn * 32 + nt * 8 + g;
                uint32_t b0 = Bs[kk + t][c0];
                uint32_t b1 = Bs[kk + t + 4][c0];
#pragma unroll
                for (int mt = 0; mt < 4; mt++)
                    mma_tf32(acc[mt][nt], a[mt], b0, b1);
            }
        }
    }

    // epilogue: tanh(acc + qW) * wv, partial-sum over this warp's 32 cols
    float s[8];
#pragma unroll
    for (int i = 0; i < 8; i++) s[i] = 0.f;
#pragma unroll
    for (int mt = 0; mt < 4; mt++) {
#pragma unroll
        for (int nt = 0; nt < 4; nt++) {
            int col = bn * 128 + wn * 32 + nt * 8 + 2 * t;
            float qw0 = g_qW[col], qw1 = g_qW[col + 1];
            float w0 = wv[col], w1 = wv[col + 1];
            s[mt * 2 + 0] += tanhf(acc[mt][nt][0] + qw0) * w0 + tanhf(acc[mt][nt][1] + qw1) * w1;
            s[mt * 2 + 1] += tanhf(acc[mt][nt][2] + qw0) * w0 + tanhf(acc[mt][nt][3] + qw1) * w1;
        }
    }
#pragma unroll
    for (int i = 0; i < 8; i++) {
        s[i] += __shfl_xor_sync(0xffffffffu, s[i], 1);
        s[i] += __shfl_xor_sync(0xffffffffu, s[i], 2);
    }
    if (t == 0) {
        int p = bn * 4 + wn;                       // 0..31
        int rowbase = bm * 128 + wm * 64;
#pragma unroll
        for (int mt = 0; mt < 4; mt++) {
            g_scorep[(size_t)p * L + rowbase + mt * 16 + g]     = s[2 * mt];
            g_scorep[(size_t)p * L + rowbase + mt * 16 + g + 8] = s[2 * mt + 1];
        }
    }
}

// ---------------- softmax chain (parallel, normalization deferred) -------------
__global__ void k_sm_reduce_max() {          // 16 blocks x 256
    __shared__ float sred[256];
    int tid = threadIdx.x;
    int l = blockIdx.x * 256 + tid;
    float s = 0.f;
#pragma unroll
    for (int p = 0; p < NPART; p++) s += g_scorep[(size_t)p * L + l];
    g_scores[l] = s;
    sred[tid] = s;
    __syncthreads();
    for (int o = 128; o > 0; o >>= 1) {
        if (tid < o) sred[tid] = fmaxf(sred[tid], sred[tid + o]);
        __syncthreads();
    }
    if (tid == 0) g_mpart[blockIdx.x] = sred[0];
}

__global__ void k_sm_gmax() {                // 1 block x 32
    int lane = threadIdx.x;
    float m = (lane < 16) ? g_mpart[lane] : -INFINITY;
#pragma unroll
    for (int o = 16; o > 0; o >>= 1) m = fmaxf(m, __shfl_xor_sync(0xffffffffu, m, o));
    if (lane == 0) g_gmax = m;
}

__global__ void k_sm_exp() {                 // 16 blocks x 256
    __shared__ float sred[256];
    int tid = threadIdx.x;
    int l = blockIdx.x * 256 + tid;
    float e = expf(g_scores[l] - g_gmax);
    g_attn[l] = e;
    sred[tid] = e;
    __syncthreads();
    for (int o = 128; o > 0; o >>= 1) {
        if (tid < o) sred[tid] += sred[tid + o];
        __syncthreads();
    }
    if (tid == 0) g_spart[blockIdx.x] = sred[0];
}

__global__ void k_sm_sum() {                 // 1 block x 32
    int lane = threadIdx.x;
    float s = (lane < 16) ? g_spart[lane] : 0.f;
#pragma unroll
    for (int o = 16; o > 0; o >>= 1) s += __shfl_xor_sync(0xffffffffu, s, o);
    if (lane == 0) g_invS = 1.0f / s;
}

// ---------------- K5: context partials (grid 8 j x 32 lc, 128 thr) -------------
__global__ void k_ctx_partial(const float* __restrict__ enc) {
    int j  = blockIdx.x * 128 + threadIdx.x;
    int l0 = blockIdx.y * 128;
    float acc = 0.f;
#pragma unroll 8
    for (int l = l0; l < l0 + 128; l++)
        acc += g_attn[l] * enc[(size_t)l * H + j];
    g_ctxp[blockIdx.y * H + j] = acc;
}

// ---------------- K6: x = concat(invS * ctx, relu(emb[token])) -----------------
__global__ void k_build_x(const int* __restrict__ input, const float* __restrict__ emb) {
    int idx = blockIdx.x * 256 + threadIdx.x;
    if (idx < H) {
        float s = 0.f;
#pragma unroll
        for (int p = 0; p < 32; p++) s += g_ctxp[p * H + idx];
        g_x[idx] = s * g_invS;
    } else {
        int tok = input[0];
        float e = emb[(size_t)tok * H + (idx - H)];
        g_x[idx] = fmaxf(e, 0.f);
    }
}

// ---------------- K7: GRU GEMVs (templated xlen for full unroll) ---------------
template <int XLEN>
__global__ void k_gru_gemv(const float* __restrict__ Wi, const float* __restrict__ Wh,
                           const float* __restrict__ bi, const float* __restrict__ bh,
                           const float* __restrict__ x, const float* __restrict__ h) {
    __shared__ float sxh[XLEN + H];
    int tid = threadIdx.x;
    for (int i = tid; i < XLEN; i += 256) sxh[i] = x[i];
    for (int i = tid; i < H; i += 256) sxh[XLEN + i] = h[i];
    __syncthreads();

    int warp = blockIdx.x * 8 + (tid >> 5);
    int lane = tid & 31;
    if (warp < G3) {
        const float* W = Wi + (size_t)warp * XLEN;
        float acc = 0.f;
#pragma unroll
        for (int c0 = 0; c0 < XLEN; c0 += 128) {
            int c = c0 + lane * 4;
            float4 w = *(const float4*)(W + c);
            acc += w.x * sxh[c] + w.y * sxh[c + 1] + w.z * sxh[c + 2] + w.w * sxh[c + 3];
        }
#pragma unroll
        for (int o = 16; o > 0; o >>= 1) acc += __shfl_down_sync(0xffffffffu, acc, o);
        if (lane == 0) g_gi[warp] = acc + bi[warp];
    } else {
        int r = warp - G3;
        const float* W = Wh + (size_t)r * H;
        float acc = 0.f;
#pragma unroll
        for (int c0 = 0; c0 < H; c0 += 128) {
            int c = c0 + lane * 4;
            float4 w = *(const float4*)(W + c);
            acc += w.x * sxh[XLEN + c] + w.y * sxh[XLEN + c + 1] + w.z * sxh[XLEN + c + 2] + w.w * sxh[XLEN + c + 3];
        }
#pragma unroll
        for (int o = 16; o > 0; o >>= 1) acc += __shfl_down_sync(0xffffffffu, acc, o);
        if (lane == 0) g_gh[r] = acc + bh[r];
    }
}

// ---------------- K8: GRU elementwise combine ----------------
__global__ void k_gru_combine(const float* __restrict__ h_prev,
                              float* __restrict__ h_scratch,
                              float* __restrict__ out_hidden) {
    int k = blockIdx.x * 256 + threadIdx.x;
    float r = sigmoidf_(g_gi[k] + g_gh[k]);
    float z = sigmoidf_(g_gi[k + H] + g_gh[k + H]);
    float n = tanhf(g_gi[k + 2 * H] + r * g_gh[k + 2 * H]);
    float hp = h_prev[k];
    float hn = (1.0f - z) * n + z * hp;
    h_scratch[k] = hn;
    out_hidden[k] = hn;
}

// ---------------- K11: logits GEMV + per-block softmax stats -------------------
__global__ void k_logits(const float* __restrict__ Wd, const float* __restrict__ bd,
                         float* __restrict__ out) {
    __shared__ float sh[H];
    __shared__ float sred[256];
    int tid = threadIdx.x;
    for (int i = tid; i < H; i += 256) sh[i] = g_h1n[i];
    __syncthreads();

    int v = blockIdx.x * 256 + tid;
    float acc = -INFINITY;
    if (v < V) {
        acc = bd[v];
#pragma unroll 16
        for (int h = 0; h < H; h++)
            acc += sh[h] * Wd[(size_t)h * V + v];
        out[v] = acc;
    }
    sred[tid] = acc;
    __syncthreads();
    for (int o = 128; o > 0; o >>= 1) {
        if (tid < o) sred[tid] = fmaxf(sred[tid], sred[tid + o]);
        __syncthreads();
    }
    float bm = sred[0];
    __syncthreads();
    sred[tid] = (v < V) ? expf(acc - bm) : 0.f;
    __syncthreads();
    for (int o = 128; o > 0; o >>= 1) {
        if (tid < o) sred[tid] += sred[tid + o];
        __syncthreads();
    }
    if (tid == 0) {
        g_mpart[blockIdx.x] = bm;
        g_spart[blockIdx.x] = sred[0];
    }
}

__global__ void k_lse_combine(int nparts) {
    __shared__ float sm[256];
    __shared__ float ss[256];
    int t = threadIdx.x;
    float m = (t < nparts) ? g_mpart[t] : -INFINITY;
    sm[t] = m;
    __syncthreads();
    for (int o = 128; o > 0; o >>= 1) {
        if (t < o) sm[t] = fmaxf(sm[t], sm[t + o]);
        __syncthreads();
    }
    float M = sm[0];
    float s = (t < nparts) ? g_spart[t] * expf(g_mpart[t] - M) : 0.f;
    ss[t] = s;
    __syncthreads();
    for (int o = 128; o > 0; o >>= 1) {
        if (t < o) ss[t] += ss[t + o];
        __syncthreads();
    }
    if (t == 0) g_lse = M + logf(ss[0]);
}

__global__ void k_logp_final(float* __restrict__ out) {
    int v = blockIdx.x * 256 + threadIdx.x;
    if (v < V) out[v] = out[v] - g_lse;
}

// ---------------- launcher ----------------
extern "C" void kernel_launch(void* const* d_in, const int* in_sizes, int n_in,
                              void* d_out, int out_size) {
    const int*   input  = (const int*)d_in[0];
    const float* hidden = (const float*)d_in[1];
    const float* enc    = (const float*)d_in[2];
    const float* emb    = (const float*)d_in[3];
    const float* Wq     = (const float*)d_in[4];
    const float* Wk     = (const float*)d_in[5];
    const float* wv     = (const float*)d_in[6];
    const float* W_ih0  = (const float*)d_in[7];
    const float* W_hh0  = (const float*)d_in[8];
    const float* b_ih0  = (const float*)d_in[9];
    const float* b_hh0  = (const float*)d_in[10];
    const float* W_ih1  = (const float*)d_in[11];
    const float* W_hh1  = (const float*)d_in[12];
    const float* b_ih1  = (const float*)d_in[13];
    const float* b_hh1  = (const float*)d_in[14];
    const float* Wd     = (const float*)d_in[15];
    const float* bd     = (const float*)d_in[16];

    float* out = (float*)d_out;  // [0,V) logp ; [V, V+2048) new hidden

    float* g_h0n_p; cudaGetSymbolAddress((void**)&g_h0n_p, g_h0n);
    float* g_h1n_p; cudaGetSymbolAddress((void**)&g_h1n_p, g_h1n);
    float* g_x_p;   cudaGetSymbolAddress((void**)&g_x_p, g_x);

    k_qw_partial<<<dim3(4, 32), 256>>>(hidden, Wq);
    k_qw_reduce<<<4, 256>>>();
    k_attn_gemm_mma<<<dim3(8, 32), 256>>>(enc, Wk, wv);
    k_sm_reduce_max<<<16, 256>>>();
    k_sm_gmax<<<1, 32>>>();
    k_sm_exp<<<16, 256>>>();
    k_sm_sum<<<1, 32>>>();
    k_ctx_partial<<<dim3(8, 32), 128>>>(enc);
    k_build_x<<<8, 256>>>(input, emb);
    k_gru_gemv<X2><<<768, 256>>>(W_ih0, W_hh0, b_ih0, b_hh0, g_x_p, hidden);
    k_gru_combine<<<4, 256>>>(hidden, g_h0n_p, out + V);
    k_gru_gemv<H><<<768, 256>>>(W_ih1, W_hh1, b_ih1, b_hh1, g_h0n_p, hidden + H);
    k_gru_combine<<<4, 256>>>(hidden + H, g_h1n_p, out + V + H);
    const int nblk = (V + 255) / 256;  // 197
    k_logits<<<nblk, 256>>>(Wd, bd, out);
    k_lse_combine<<<1, 256>>>(nblk);
    k_logp_final<<<nblk, 256>>>(out);
}

// round 4
// speedup vs baseline: 2.8180x; 1.2190x over previous
#include <cuda_runtime.h>
#include <cuda_bf16.h>
#include <math.h>
#include <stdint.h>

#define H 1024
#define L 4096
#define V 50257
#define G3 3072
#define X2 2048

#define NPART 8    // score partials per row (8 bn-blocks, reduced in-block)

// ---------------- scratch (device globals, no allocation) ----------------
__device__ float g_qwp[32 * H];       // qW partials
__device__ float g_qW[H];             // query @ Wq
__device__ float g_scorep[NPART * L]; // [bn][l] partial scores
__device__ float g_attn[L];           // UNNORMALIZED exp(s - max)
__device__ float g_invS;              // 1/sum(exp)
__device__ float g_ctxp[32 * H];      // context partials
__device__ float g_x[X2];             // concat(context, relu(emb))
__device__ float g_gi0[G3], g_gh0[G3];// GRU layer-0 gates
__device__ float g_gi1[G3], g_gh1[G3];// GRU layer-1 gates
__device__ float g_mpart[256];        // logsumexp partial max
__device__ float g_spart[256];        // logsumexp partial sum
__device__ float g_lse;               // final logsumexp

__device__ __forceinline__ float sigmoidf_(float x) { return 1.0f / (1.0f + expf(-x)); }

__device__ __forceinline__ uint32_t pk(float lo, float hi) {
    __nv_bfloat162 v = __floats2bfloat162_rn(lo, hi);
    return *(uint32_t*)&v;
}

__device__ __forceinline__ void mma_bf16(float c[4], const uint32_t a[4],
                                         uint32_t b0, uint32_t b1) {
    asm volatile(
        "mma.sync.aligned.m16n8k16.row.col.f32.bf16.bf16.f32 "
        "{%0,%1,%2,%3}, {%4,%5,%6,%7}, {%8,%9}, {%0,%1,%2,%3};"
        : "+f"(c[0]), "+f"(c[1]), "+f"(c[2]), "+f"(c[3])
        : "r"(a[0]), "r"(a[1]), "r"(a[2]), "r"(a[3]), "r"(b0), "r"(b1));
}

// ---------------- K1: qW partials (grid 4 j x 32 i, 256 thr) ----------------
__global__ void k_qw_partial(const float* __restrict__ hidden, const float* __restrict__ Wq) {
    int j  = blockIdx.x * 256 + threadIdx.x;
    int i0 = blockIdx.y * 32;
    const float* q = hidden + H;
    float acc = 0.f;
#pragma unroll
    for (int i = 0; i < 32; i++)
        acc += q[i0 + i] * Wq[(size_t)(i0 + i) * H + j];
    g_qwp[blockIdx.y * H + j] = acc;
}

__global__ void k_qw_reduce() {
    int j = blockIdx.x * 256 + threadIdx.x;
    float s = 0.f;
#pragma unroll
    for (int p = 0; p < 32; p++) s += g_qwp[p * H + j];
    g_qW[j] = s;
}

// ---------------- K3: attention GEMM, bf16 m16n8k16, pipelined -----------------
// BM=128, BN=128, BK=32 floats (16 bf16x2); 8 warps = 2(m) x 4(n); warp 64x32.
__global__ void __launch_bounds__(256, 2)
k_attn_gemm_mma(const float* __restrict__ enc, const float* __restrict__ Wk,
                const float* __restrict__ wv) {
    __shared__ uint32_t As[128][20];   // [m][k2] bf16x2, pad 20
    __shared__ uint32_t Bs[16][136];   // [k2][n] bf16x2, pad 136
    __shared__ float red[128][4];      // cross-warp score reduce

    const int tid  = threadIdx.x;
    const int warp = tid >> 5, lane = tid & 31;
    const int wm = warp & 1, wn = warp >> 1;
    const int g = lane >> 2, t = lane & 3;
    const int bn = blockIdx.x, bm = blockIdx.y;

    float acc[4][4][4];
#pragma unroll
    for (int mt = 0; mt < 4; mt++)
#pragma unroll
        for (int nt = 0; nt < 4; nt++)
#pragma unroll
            for (int i = 0; i < 4; i++) acc[mt][nt][i] = 0.f;

    // A producer: rows {arow, arow+64}, k floats akc..akc+7
    const int arow = tid >> 2;
    const int akc  = (tid & 3) * 8;          // float k offset
    const int ak2  = (tid & 3) * 4;          // k2 offset in smem
    const float* Ab = enc + (size_t)(bm * 128 + arow) * H + akc;
    // B producer: k2 slots {bk, bk+8} -> k rows {2bk,2bk+1,2bk+16,2bk+17}
    const int bk  = tid >> 5;
    const int bnc = lane * 4;
    const float* Bb = Wk + (size_t)(2 * bk) * H + bn * 128 + bnc;

    float4 a00, a01, a10, a11, b00, b01, b10, b11;
    a00 = *(const float4*)(Ab);
    a01 = *(const float4*)(Ab + 4);
    a10 = *(const float4*)(Ab + (size_t)64 * H);
    a11 = *(const float4*)(Ab + (size_t)64 * H + 4);
    b00 = *(const float4*)(Bb);
    b01 = *(const float4*)(Bb + (size_t)H);
    b10 = *(const float4*)(Bb + (size_t)16 * H);
    b11 = *(const float4*)(Bb + (size_t)17 * H);

    for (int it = 0; it < 32; ++it) {
        __syncthreads();
        *(uint4*)&As[arow][ak2] =
            make_uint4(pk(a00.x, a00.y), pk(a00.z, a00.w), pk(a01.x, a01.y), pk(a01.z, a01.w));
        *(uint4*)&As[arow + 64][ak2] =
            make_uint4(pk(a10.x, a10.y), pk(a10.z, a10.w), pk(a11.x, a11.y), pk(a11.z, a11.w));
        *(uint4*)&Bs[bk][bnc] =
            make_uint4(pk(b00.x, b01.x), pk(b00.y, b01.y), pk(b00.z, b01.z), pk(b00.w, b01.w));
        *(uint4*)&Bs[bk + 8][bnc] =
            make_uint4(pk(b10.x, b11.x), pk(b10.y, b11.y), pk(b10.z, b11.z), pk(b10.w, b11.w));
        __syncthreads();

        if (it < 31) {
            size_t k0 = (size_t)(it + 1) * 32;
            a00 = *(const float4*)(Ab + k0);
            a01 = *(const float4*)(Ab + k0 + 4);
            a10 = *(const float4*)(Ab + (size_t)64 * H + k0);
            a11 = *(const float4*)(Ab + (size_t)64 * H + k0 + 4);
            b00 = *(const float4*)(Bb + k0 * H);
            b01 = *(const float4*)(Bb + (k0 + 1) * H);
            b10 = *(const float4*)(Bb + (k0 + 16) * H);
            b11 = *(const float4*)(Bb + (k0 + 17) * H);
        }

#pragma unroll
        for (int ks = 0; ks < 2; ks++) {
            const int kk = ks * 8;
            uint32_t a[4][4];
#pragma unroll
            for (int mt = 0; mt < 4; mt++) {
                int r0 = wm * 64 + mt * 16 + g;
                a[mt][0] = As[r0][kk + t];
                a[mt][1] = As[r0 + 8][kk + t];
                a[mt][2] = As[r0][kk + t + 4];
                a[mt][3] = As[r0 + 8][kk + t + 4];
            }
#pragma unroll
            for (int nt = 0; nt < 4; nt++) {
                int c0 = wn * 32 + nt * 8 + g;
                uint32_t b0 = Bs[kk + t][c0];
                uint32_t b1 = Bs[kk + t + 4][c0];
#pragma unroll
                for (int mt = 0; mt < 4; mt++)
                    mma_bf16(acc[mt][nt], a[mt], b0, b1);
            }
        }
    }

    // epilogue: tanh(acc + qW) * wv, reduce over warp's 32 cols, then cross-warp
    float s[8];
#pragma unroll
    for (int i = 0; i < 8; i++) s[i] = 0.f;
#pragma unroll
    for (int mt = 0; mt < 4; mt++) {
#pragma unroll
        for (int nt = 0; nt < 4; nt++) {
            int col = bn * 128 + wn * 32 + nt * 8 + 2 * t;
            float qw0 = g_qW[col], qw1 = g_qW[col + 1];
            float w0 = wv[col], w1 = wv[col + 1];
            s[mt * 2 + 0] += tanhf(acc[mt][nt][0] + qw0) * w0 + tanhf(acc[mt][nt][1] + qw1) * w1;
            s[mt * 2 + 1] += tanhf(acc[mt][nt][2] + qw0) * w0 + tanhf(acc[mt][nt][3] + qw1) * w1;
        }
    }
#pragma unroll
    for (int i = 0; i < 8; i++) {
        s[i] += __shfl_xor_sync(0xffffffffu, s[i], 1);
        s[i] += __shfl_xor_sync(0xffffffffu, s[i], 2);
    }
    __syncthreads();
    if (t == 0) {
#pragma unroll
        for (int mt = 0; mt < 4; mt++) {
            red[wm * 64 + mt * 16 + g][wn]     = s[2 * mt];
            red[wm * 64 + mt * 16 + g + 8][wn] = s[2 * mt + 1];
        }
    }
    __syncthreads();
    if (tid < 128) {
        float v = red[tid][0] + red[tid][1] + red[tid][2] + red[tid][3];
        g_scorep[(size_t)bn * L + bm * 128 + tid] = v;
    }
}

// ---------------- K4: fused softmax over L (1 block x 1024) --------------------
__global__ void k_softmax() {
    __shared__ float sred[32];
    int tid = threadIdx.x;
    int wid = tid >> 5, lane = tid & 31;
    float v[4];
    float mx = -INFINITY;
#pragma unroll
    for (int tt = 0; tt < 4; tt++) {
        int l = tt * 1024 + tid;
        float s = 0.f;
#pragma unroll
        for (int p = 0; p < NPART; p++) s += g_scorep[(size_t)p * L + l];
        v[tt] = s;
        mx = fmaxf(mx, s);
    }
#pragma unroll
    for (int o = 16; o > 0; o >>= 1) mx = fmaxf(mx, __shfl_xor_sync(0xffffffffu, mx, o));
    if (lane == 0) sred[wid] = mx;
    __syncthreads();
    if (wid == 0) {
        float m = sred[lane];
#pragma unroll
        for (int o = 16; o > 0; o >>= 1) m = fmaxf(m, __shfl_xor_sync(0xffffffffu, m, o));
        sred[lane] = m;
    }
    __syncthreads();
    float M = sred[0];
    __syncthreads();
    float e[4], s = 0.f;
#pragma unroll
    for (int tt = 0; tt < 4; tt++) { e[tt] = expf(v[tt] - M); s += e[tt]; }
#pragma unroll
    for (int o = 16; o > 0; o >>= 1) s += __shfl_xor_sync(0xffffffffu, s, o);
    if (lane == 0) sred[wid] = s;
    __syncthreads();
    if (wid == 0) {
        float q = sred[lane];
#pragma unroll
        for (int o = 16; o > 0; o >>= 1) q += __shfl_xor_sync(0xffffffffu, q, o);
        if (lane == 0) g_invS = 1.0f / q;
    }
#pragma unroll
    for (int tt = 0; tt < 4; tt++) g_attn[tt * 1024 + tid] = e[tt];
}

// ---------------- K5: context partials (grid 8 j x 32 lc, 128 thr) -------------
__global__ void k_ctx_partial(const float* __restrict__ enc) {
    int j  = blockIdx.x * 128 + threadIdx.x;
    int l0 = blockIdx.y * 128;
    float acc = 0.f;
#pragma unroll 8
    for (int l = l0; l < l0 + 128; l++)
        acc += g_attn[l] * enc[(size_t)l * H + j];
    g_ctxp[blockIdx.y * H + j] = acc;
}

// ---------------- K6: x = concat(invS * ctx, relu(emb[token])) -----------------
__global__ void k_build_x(const int* __restrict__ input, const float* __restrict__ emb) {
    int idx = blockIdx.x * 256 + threadIdx.x;
    if (idx < H) {
        float s = 0.f;
#pragma unroll
        for (int p = 0; p < 32; p++) s += g_ctxp[p * H + idx];
        g_x[idx] = s * g_invS;
    } else {
        int tok = input[0];
        float e = emb[(size_t)tok * H + (idx - H)];
        g_x[idx] = fmaxf(e, 0.f);
    }
}

// ---------------- K7: GRU layer-0 GEMV (xlen 2048) ----------------
__global__ void k_gru_gemv0(const float* __restrict__ Wi, const float* __restrict__ Wh,
                            const float* __restrict__ bi, const float* __restrict__ bh,
                            const float* __restrict__ hidden) {
    __shared__ float sxh[X2 + H];
    int tid = threadIdx.x;
    for (int i = tid; i < X2; i += 256) sxh[i] = g_x[i];
    for (int i = tid; i < H; i += 256) sxh[X2 + i] = hidden[i];   // layer-0 h
    __syncthreads();

    int warp = blockIdx.x * 8 + (tid >> 5);
    int lane = tid & 31;
    if (warp < G3) {
        const float* W = Wi + (size_t)warp * X2;
        float acc = 0.f;
#pragma unroll
        for (int c0 = 0; c0 < X2; c0 += 128) {
            int c = c0 + lane * 4;
            float4 w = *(const float4*)(W + c);
            acc += w.x * sxh[c] + w.y * sxh[c + 1] + w.z * sxh[c + 2] + w.w * sxh[c + 3];
        }
#pragma unroll
        for (int o = 16; o > 0; o >>= 1) acc += __shfl_down_sync(0xffffffffu, acc, o);
        if (lane == 0) g_gi0[warp] = acc + bi[warp];
    } else {
        int r = warp - G3;
        const float* W = Wh + (size_t)r * H;
        float acc = 0.f;
#pragma unroll
        for (int c0 = 0; c0 < H; c0 += 128) {
            int c = c0 + lane * 4;
            float4 w = *(const float4*)(W + c);
            acc += w.x * sxh[X2 + c] + w.y * sxh[X2 + c + 1] + w.z * sxh[X2 + c + 2] + w.w * sxh[X2 + c + 3];
        }
#pragma unroll
        for (int o = 16; o > 0; o >>= 1) acc += __shfl_down_sync(0xffffffffu, acc, o);
        if (lane == 0) g_gh0[r] = acc + bh[r];
    }
}

// ---------------- K8: GRU layer-1 GEMV, fused layer-0 combine -------------------
__global__ void k_gru_gemv1(const float* __restrict__ Wi, const float* __restrict__ Wh,
                            const float* __restrict__ bi, const float* __restrict__ bh,
                            const float* __restrict__ hidden, float* __restrict__ out_h0) {
    __shared__ float sxh[2 * H];
    int tid = threadIdx.x;
    // prologue: h0n from layer-0 gates (redundant per block; fixed order)
    for (int i = tid; i < H; i += 256) {
        float r = sigmoidf_(g_gi0[i] + g_gh0[i]);
        float z = sigmoidf_(g_gi0[i + H] + g_gh0[i + H]);
        float n = tanhf(g_gi0[i + 2 * H] + r * g_gh0[i + 2 * H]);
        float hn = (1.0f - z) * n + z * hidden[i];
        sxh[i] = hn;
        if (blockIdx.x == 0) out_h0[i] = hn;
        sxh[H + i] = hidden[H + i];   // layer-1 h
    }
    __syncthreads();

    int warp = blockIdx.x * 8 + (tid >> 5);
    int lane = tid & 31;
    const float* W = (warp < G3) ? (Wi + (size_t)warp * H)
                                 : (Wh + (size_t)(warp - G3) * H);
    const float* xv = (warp < G3) ? sxh : (sxh + H);
    float acc = 0.f;
#pragma unroll
    for (int c0 = 0; c0 < H; c0 += 128) {
        int c = c0 + lane * 4;
        float4 w = *(const float4*)(W + c);
        acc += w.x * xv[c] + w.y * xv[c + 1] + w.z * xv[c + 2] + w.w * xv[c + 3];
    }
#pragma unroll
    for (int o = 16; o > 0; o >>= 1) acc += __shfl_down_sync(0xffffffffu, acc, o);
    if (lane == 0) {
        if (warp < G3) g_gi1[warp] = acc + bi[warp];
        else           g_gh1[warp - G3] = acc + bh[warp - G3];
    }
}

// ---------------- K9: logits GEMV (fused layer-1 combine) + softmax stats ------
__global__ void k_logits(const float* __restrict__ Wd, const float* __restrict__ bd,
                         const float* __restrict__ hidden, float* __restrict__ out,
                         float* __restrict__ out_h1) {
    __shared__ float sh[H];
    __shared__ float sred[256];
    int tid = threadIdx.x;
    for (int i = tid; i < H; i += 256) {
        float r = sigmoidf_(g_gi1[i] + g_gh1[i]);
        float z = sigmoidf_(g_gi1[i + H] + g_gh1[i + H]);
        float n = tanhf(g_gi1[i + 2 * H] + r * g_gh1[i + 2 * H]);
        float hn = (1.0f - z) * n + z * hidden[H + i];
        sh[i] = hn;
        if (blockIdx.x == 0) out_h1[i] = hn;
    }
    __syncthreads();

    int v = blockIdx.x * 256 + tid;
    float acc = -INFINITY;
    if (v < V) {
        acc = bd[v];
#pragma unroll 16
        for (int h = 0; h < H; h++)
            acc += sh[h] * Wd[(size_t)h * V + v];
        out[v] = acc;
    }
    sred[tid] = acc;
    __syncthreads();
    for (int o = 128; o > 0; o >>= 1) {
        if (tid < o) sred[tid] = fmaxf(sred[tid], sred[tid + o]);
        __syncthreads();
    }
    float bm = sred[0];
    __syncthreads();
    sred[tid] = (v < V) ? expf(acc - bm) : 0.f;
    __syncthreads();
    for (int o = 128; o > 0; o >>= 1) {
        if (tid < o) sred[tid] += sred[tid + o];
        __syncthreads();
    }
    if (tid == 0) {
        g_mpart[blockIdx.x] = bm;
        g_spart[blockIdx.x] = sred[0];
    }
}

__global__ void k_lse_combine(int nparts) {
    __shared__ float sm[256];
    __shared__ float ss[256];
    int t = threadIdx.x;
    float m = (t < nparts) ? g_mpart[t] : -INFINITY;
    sm[t] = m;
    __syncthreads();
    for (int o = 128; o > 0; o >>= 1) {
        if (t < o) sm[t] = fmaxf(sm[t], sm[t + o]);
        __syncthreads();
    }
    float M = sm[0];
    float s = (t < nparts) ? g_spart[t] * expf(g_mpart[t] - M) : 0.f;
    ss[t] = s;
    __syncthreads();
    for (int o = 128; o > 0; o >>= 1) {
        if (t < o) ss[t] += ss[t + o];
        __syncthreads();
    }
    if (t == 0) g_lse = M + logf(ss[0]);
}

__global__ void k_logp_final(float* __restrict__ out) {
    int v = blockIdx.x * 256 + threadIdx.x;
    if (v < V) out[v] = out[v] - g_lse;
}

// ---------------- launcher ----------------
extern "C" void kernel_launch(void* const* d_in, const int* in_sizes, int n_in,
                              void* d_out, int out_size) {
    const int*   input  = (const int*)d_in[0];
    const float* hidden = (const float*)d_in[1];
    const float* enc    = (const float*)d_in[2];
    const float* emb    = (const float*)d_in[3];
    const float* Wq     = (const float*)d_in[4];
    const float* Wk     = (const float*)d_in[5];
    const float* wv     = (const float*)d_in[6];
    const float* W_ih0  = (const float*)d_in[7];
    const float* W_hh0  = (const float*)d_in[8];
    const float* b_ih0  = (const float*)d_in[9];
    const float* b_hh0  = (const float*)d_in[10];
    const float* W_ih1  = (const float*)d_in[11];
    const float* W_hh1  = (const float*)d_in[12];
    const float* b_ih1  = (const float*)d_in[13];
    const float* b_hh1  = (const float*)d_in[14];
    const float* Wd     = (const float*)d_in[15];
    const float* bd     = (const float*)d_in[16];

    float* out = (float*)d_out;  // [0,V) logp ; [V,V+H) h0n ; [V+H,V+2H) h1n

    k_qw_partial<<<dim3(4, 32), 256>>>(hidden, Wq);
    k_qw_reduce<<<4, 256>>>();
    k_attn_gemm_mma<<<dim3(8, 32), 256>>>(enc, Wk, wv);
    k_softmax<<<1, 1024>>>();
    k_ctx_partial<<<dim3(8, 32), 128>>>(enc);
    k_build_x<<<8, 256>>>(input, emb);
    k_gru_gemv0<<<768, 256>>>(W_ih0, W_hh0, b_ih0, b_hh0, hidden);
    k_gru_gemv1<<<768, 256>>>(W_ih1, W_hh1, b_ih1, b_hh1, hidden, out + V);
    const int nblk = (V + 255) / 256;  // 197
    k_logits<<<nblk, 256>>>(Wd, bd, hidden, out, out + V + H);
    k_lse_combine<<<1, 256>>>(nblk);
    k_logp_final<<<nblk, 256>>>(out);
}

// round 5
// speedup vs baseline: 2.8958x; 1.0276x over previous
#include <cuda_runtime.h>
#include <cuda_bf16.h>
#include <math.h>
#include <stdint.h>

#define H 1024
#define L 4096
#define V 50257
#define G3 3072
#define X2 2048
#define NPART 8
#define VP 50432           // 197*256

// ---------------- scratch (device globals, no allocation) ----------------
__device__ __nv_bfloat16 g_encb[L * H];   // bf16 enc
__device__ uint32_t g_wkb[(H / 2) * H];   // Wk packed bf16x2 along k: [k2][n]
__device__ float g_qwp[32 * H];           // qW partials
__device__ float g_scorep[NPART * L];     // [bn][l] partial scores
__device__ float g_attn[L];               // UNNORMALIZED exp(s - max)
__device__ float g_invS;                  // 1/sum(exp)
__device__ float g_ctxp[32 * H];          // context partials
__device__ float g_x[X2];                 // concat(context, relu(emb))
__device__ float g_gi0[G3], g_gh0[G3];    // GRU layer-0 gates
__device__ float g_gi1[G3], g_gh1[G3];    // GRU layer-1 gates
__device__ float g_logitp[4 * VP];        // split-K logits partials
__device__ float g_mpart[256];
__device__ float g_spart[256];
__device__ float g_lse;

__device__ __forceinline__ float sigmoidf_(float x) { return 1.0f / (1.0f + expf(-x)); }

__device__ __forceinline__ uint32_t pk(float lo, float hi) {
    __nv_bfloat162 v = __floats2bfloat162_rn(lo, hi);
    return *(uint32_t*)&v;
}

__device__ __forceinline__ void mma_bf16(float c[4], const uint32_t a[4],
                                         uint32_t b0, uint32_t b1) {
    asm volatile(
        "mma.sync.aligned.m16n8k16.row.col.f32.bf16.bf16.f32 "
        "{%0,%1,%2,%3}, {%4,%5,%6,%7}, {%8,%9}, {%0,%1,%2,%3};"
        : "+f"(c[0]), "+f"(c[1]), "+f"(c[2]), "+f"(c[3])
        : "r"(a[0]), "r"(a[1]), "r"(a[2]), "r"(a[3]), "r"(b0), "r"(b1));
}

__device__ __forceinline__ void cpa16(uint32_t dst, const void* src) {
    asm volatile("cp.async.cg.shared.global [%0], [%1], 16;\n"
                 :: "r"(dst), "l"(__cvta_generic_to_global(src)));
}

// ---------------- converts ----------------
__global__ void k_cvt_enc(const float* __restrict__ enc) {
    int idx = (blockIdx.x * 256 + threadIdx.x) * 4;
    float4 v = *(const float4*)(enc + idx);
    uint2 o = make_uint2(pk(v.x, v.y), pk(v.z, v.w));
    *(uint2*)&g_encb[idx] = o;
}

__global__ void k_cvt_wk(const float* __restrict__ Wk) {
    int idx = blockIdx.x * 256 + threadIdx.x;   // 0..524287
    int i = idx >> 10, n = idx & 1023;
    g_wkb[idx] = pk(Wk[(size_t)(2 * i) * H + n], Wk[(size_t)(2 * i + 1) * H + n]);
}

// ---------------- K1: qW partials (grid 4 j x 32 i, 256 thr) ----------------
__global__ void k_qw_partial(const float* __restrict__ hidden, const float* __restrict__ Wq) {
    int j  = blockIdx.x * 256 + threadIdx.x;
    int i0 = blockIdx.y * 32;
    const float* q = hidden + H;
    float acc = 0.f;
#pragma unroll
    for (int i = 0; i < 32; i++)
        acc += q[i0 + i] * Wq[(size_t)(i0 + i) * H + j];
    g_qwp[blockIdx.y * H + j] = acc;
}

// ---------------- K3: attention GEMM, bf16, BM=256 BN=128, cp.async 2-stage ----
// grid (8 bn, 16 bm), 256 threads = 8 warps (4m x 2n), warp tile 64x64.
#define GEMM_SMEM_U32 14848
__global__ void __launch_bounds__(256, 1)
k_attn_gemm(const float* __restrict__ wv) {
    extern __shared__ uint32_t sm[];
    uint32_t* As0 = sm;                 // [256][20]
    uint32_t* As1 = sm + 5120;
    uint32_t* Bs0 = sm + 10240;         // [16][136]
    uint32_t* Bs1 = sm + 12416;
    float* sqw = (float*)(sm + 14592);  // 128
    float* swv = sqw + 128;             // 128

    const int tid = threadIdx.x;
    const int warp = tid >> 5, lane = tid & 31;
    const int wm = warp >> 1, wn = warp & 1;
    const int g = lane >> 2, t = lane & 3;
    const int bn = blockIdx.x, bm = blockIdx.y;

    // fold qW partial-reduce into prologue
    if (tid < 128) {
        int col = bn * 128 + tid;
        float s = 0.f;
#pragma unroll
        for (int p = 0; p < 32; p++) s += g_qwp[p * H + col];
        sqw[tid] = s;
        swv[tid] = wv[col];
    }

    float acc[4][8][4];
#pragma unroll
    for (int mt = 0; mt < 4; mt++)
#pragma unroll
        for (int nt = 0; nt < 8; nt++)
#pragma unroll
            for (int i = 0; i < 4; i++) acc[mt][nt][i] = 0.f;

    const __nv_bfloat16* Ag = g_encb + (size_t)(bm * 256 + tid) * H;
    const uint32_t* Bg = g_wkb + (size_t)(tid >> 4) * H + bn * 128 + (tid & 15) * 8;
    const uint32_t aOff = tid * 20;
    const uint32_t bOff = (tid >> 4) * 136 + (tid & 15) * 8;
    const uint32_t as0 = (uint32_t)__cvta_generic_to_shared(As0 + aOff);
    const uint32_t as1 = (uint32_t)__cvta_generic_to_shared(As1 + aOff);
    const uint32_t bs0 = (uint32_t)__cvta_generic_to_shared(Bs0 + bOff);
    const uint32_t bs1 = (uint32_t)__cvta_generic_to_shared(Bs1 + bOff);

#define LOAD_STAGE(it, ad, bd)                                      \
    {                                                               \
        const __nv_bfloat16* asrc = Ag + (it) * 32;                 \
        cpa16((ad),      asrc);                                     \
        cpa16((ad) + 16, asrc + 8);                                 \
        cpa16((ad) + 32, asrc + 16);                                \
        cpa16((ad) + 48, asrc + 24);                                \
        const uint32_t* bsrc = Bg + (size_t)(it) * 16 * H;          \
        cpa16((bd),      bsrc);                                     \
        cpa16((bd) + 16, bsrc + 4);                                 \
        asm volatile("cp.async.commit_group;");                     \
    }

    LOAD_STAGE(0, as0, bs0);

    for (int it = 0; it < 32; ++it) {
        const int buf = it & 1;
        if (it < 31) {
            if (buf) LOAD_STAGE(it + 1, as0, bs0)
            else     LOAD_STAGE(it + 1, as1, bs1)
            asm volatile("cp.async.wait_group 1;");
        } else {
            asm volatile("cp.async.wait_group 0;");
        }
        __syncthreads();

        const uint32_t* A_ = buf ? As1 : As0;
        const uint32_t* B_ = buf ? Bs1 : Bs0;
#pragma unroll
        for (int ks = 0; ks < 2; ks++) {
            const int kk = ks * 8;
            uint32_t a[4][4];
#pragma unroll
            for (int mt = 0; mt < 4; mt++) {
                int r0 = wm * 64 + mt * 16 + g;
                a[mt][0] = A_[r0 * 20 + kk + t];
                a[mt][1] = A_[(r0 + 8) * 20 + kk + t];
                a[mt][2] = A_[r0 * 20 + kk + t + 4];
                a[mt][3] = A_[(r0 + 8) * 20 + kk + t + 4];
            }
#pragma unroll
            for (int nt = 0; nt < 8; nt++) {
                int c0 = wn * 64 + nt * 8 + g;
                uint32_t b0 = B_[(kk + t) * 136 + c0];
                uint32_t b1 = B_[(kk + t + 4) * 136 + c0];
#pragma unroll
                for (int mt = 0; mt < 4; mt++)
                    mma_bf16(acc[mt][nt], a[mt], b0, b1);
            }
        }
        __syncthreads();
    }

    // epilogue: tanh(acc + qW) * wv, reduce over warp's 64 cols, then over wn
    float s[8];
#pragma unroll
    for (int i = 0; i < 8; i++) s[i] = 0.f;
#pragma unroll
    for (int mt = 0; mt < 4; mt++) {
#pragma unroll
        for (int nt = 0; nt < 8; nt++) {
            int lc = wn * 64 + nt * 8 + 2 * t;
            float qw0 = sqw[lc], qw1 = sqw[lc + 1];
            float w0 = swv[lc], w1 = swv[lc + 1];
            s[mt * 2 + 0] += tanhf(acc[mt][nt][0] + qw0) * w0 + tanhf(acc[mt][nt][1] + qw1) * w1;
            s[mt * 2 + 1] += tanhf(acc[mt][nt][2] + qw0) * w0 + tanhf(acc[mt][nt][3] + qw1) * w1;
        }
    }
#pragma unroll
    for (int i = 0; i < 8; i++) {
        s[i] += __shfl_xor_sync(0xffffffffu, s[i], 1);
        s[i] += __shfl_xor_sync(0xffffffffu, s[i], 2);
    }
    __syncthreads();
    float* red = (float*)sm;     // [256][2], aliases As0 (safe post-sync)
    if (t == 0) {
#pragma unroll
        for (int mt = 0; mt < 4; mt++) {
            red[(wm * 64 + mt * 16 + g) * 2 + wn]     = s[2 * mt];
            red[(wm * 64 + mt * 16 + g + 8) * 2 + wn] = s[2 * mt + 1];
        }
    }
    __syncthreads();
    float vsum = red[tid * 2] + red[tid * 2 + 1];
    g_scorep[(size_t)bn * L + bm * 256 + tid] = vsum;
}

// ---------------- K4: fused softmax over L (1 block x 1024, float4) ------------
__global__ void k_softmax() {
    __shared__ float sred[32];
    int tid = threadIdx.x;
    int wid = tid >> 5, lane = tid & 31;
    float4 v = make_float4(0.f, 0.f, 0.f, 0.f);
#pragma unroll
    for (int p = 0; p < NPART; p++) {
        float4 sp = *(const float4*)&g_scorep[(size_t)p * L + tid * 4];
        v.x += sp.x; v.y += sp.y; v.z += sp.z; v.w += sp.w;
    }
    float mx = fmaxf(fmaxf(v.x, v.y), fmaxf(v.z, v.w));
#pragma unroll
    for (int o = 16; o > 0; o >>= 1) mx = fmaxf(mx, __shfl_xor_sync(0xffffffffu, mx, o));
    if (lane == 0) sred[wid] = mx;
    __syncthreads();
    if (wid == 0) {
        float m = sred[lane];
#pragma unroll
        for (int o = 16; o > 0; o >>= 1) m = fmaxf(m, __shfl_xor_sync(0xffffffffu, m, o));
        sred[lane] = m;
    }
    __syncthreads();
    float M = sred[0];
    __syncthreads();
    float4 e = make_float4(expf(v.x - M), expf(v.y - M), expf(v.z - M), expf(v.w - M));
    float s = e.x + e.y + e.z + e.w;
#pragma unroll
    for (int o = 16; o > 0; o >>= 1) s += __shfl_xor_sync(0xffffffffu, s, o);
    if (lane == 0) sred[wid] = s;
    __syncthreads();
    if (wid == 0) {
        float q = sred[lane];
#pragma unroll
        for (int o = 16; o > 0; o >>= 1) q += __shfl_xor_sync(0xffffffffu, q, o);
        if (lane == 0) g_invS = 1.0f / q;
    }
    *(float4*)&g_attn[tid * 4] = e;
}

// ---------------- K5: context partials (grid 8 j x 32 lc, 128 thr) -------------
__global__ void k_ctx_partial(const float* __restrict__ enc) {
    int j  = blockIdx.x * 128 + threadIdx.x;
    int l0 = blockIdx.y * 128;
    float acc = 0.f;
#pragma unroll 8
    for (int l = l0; l < l0 + 128; l++)
        acc += g_attn[l] * enc[(size_t)l * H + j];
    g_ctxp[blockIdx.y * H + j] = acc;
}

// ---------------- K6: x = concat(invS * ctx, relu(emb[token])) -----------------
__global__ void k_build_x(const int* __restrict__ input, const float* __restrict__ emb) {
    int idx = blockIdx.x * 256 + threadIdx.x;
    if (idx < H) {
        float s = 0.f;
#pragma unroll
        for (int p = 0; p < 32; p++) s += g_ctxp[p * H + idx];
        g_x[idx] = s * g_invS;
    } else {
        int tok = input[0];
        float e = emb[(size_t)tok * H + (idx - H)];
        g_x[idx] = fmaxf(e, 0.f);
    }
}

// ---------------- K7: GRU layer-0 GEMV ----------------
__global__ void k_gru_gemv0(const float* __restrict__ Wi, const float* __restrict__ Wh,
                            const float* __restrict__ bi, const float* __restrict__ bh,
                            const float* __restrict__ hidden) {
    __shared__ float sxh[X2 + H];
    int tid = threadIdx.x;
    for (int i = tid; i < X2; i += 256) sxh[i] = g_x[i];
    for (int i = tid; i < H; i += 256) sxh[X2 + i] = hidden[i];
    __syncthreads();

    int warp = blockIdx.x * 8 + (tid >> 5);
    int lane = tid & 31;
    if (warp < G3) {
        const float* W = Wi + (size_t)warp * X2;
        float acc = 0.f;
#pragma unroll
        for (int c0 = 0; c0 < X2; c0 += 128) {
            int c = c0 + lane * 4;
            float4 w = *(const float4*)(W + c);
            acc += w.x * sxh[c] + w.y * sxh[c + 1] + w.z * sxh[c + 2] + w.w * sxh[c + 3];
        }
#pragma unroll
        for (int o = 16; o > 0; o >>= 1) acc += __shfl_down_sync(0xffffffffu, acc, o);
        if (lane == 0) g_gi0[warp] = acc + bi[warp];
    } else {
        int r = warp - G3;
        const float* W = Wh + (size_t)r * H;
        float acc = 0.f;
#pragma unroll
        for (int c0 = 0; c0 < H; c0 += 128) {
            int c = c0 + lane * 4;
            float4 w = *(const float4*)(W + c);
            acc += w.x * sxh[X2 + c] + w.y * sxh[X2 + c + 1] + w.z * sxh[X2 + c + 2] + w.w * sxh[X2 + c + 3];
        }
#pragma unroll
        for (int o = 16; o > 0; o >>= 1) acc += __shfl_down_sync(0xffffffffu, acc, o);
        if (lane == 0) g_gh0[r] = acc + bh[r];
    }
}

// ---------------- K8: GRU layer-1 GEMV, fused layer-0 combine -------------------
__global__ void k_gru_gemv1(const float* __restrict__ Wi, const float* __restrict__ Wh,
                            const float* __restrict__ bi, const float* __restrict__ bh,
                            const float* __restrict__ hidden, float* __restrict__ out_h0) {
    __shared__ float sxh[2 * H];
    int tid = threadIdx.x;
    for (int i = tid; i < H; i += 256) {
        float r = sigmoidf_(g_gi0[i] + g_gh0[i]);
        float z = sigmoidf_(g_gi0[i + H] + g_gh0[i + H]);
        float n = tanhf(g_gi0[i + 2 * H] + r * g_gh0[i + 2 * H]);
        float hn = (1.0f - z) * n + z * hidden[i];
        sxh[i] = hn;
        if (blockIdx.x == 0) out_h0[i] = hn;
        sxh[H + i] = hidden[H + i];
    }
    __syncthreads();

    int warp = blockIdx.x * 8 + (tid >> 5);
    int lane = tid & 31;
    const float* W = (warp < G3) ? (Wi + (size_t)warp * H)
                                 : (Wh + (size_t)(warp - G3) * H);
    const float* xv = (warp < G3) ? sxh : (sxh + H);
    float acc = 0.f;
#pragma unroll
    for (int c0 = 0; c0 < H; c0 += 128) {
        int c = c0 + lane * 4;
        float4 w = *(const float4*)(W + c);
        acc += w.x * xv[c] + w.y * xv[c + 1] + w.z * xv[c + 2] + w.w * xv[c + 3];
    }
#pragma unroll
    for (int o = 16; o > 0; o >>= 1) acc += __shfl_down_sync(0xffffffffu, acc, o);
    if (lane == 0) {
        if (warp < G3) g_gi1[warp] = acc + bi[warp];
        else           g_gh1[warp - G3] = acc + bh[warp - G3];
    }
}

// ---------------- K9: split-K logits partials (grid 197 x 4) -------------------
__global__ void k_logits_part(const float* __restrict__ Wd, const float* __restrict__ bd,
                              const float* __restrict__ hidden, float* __restrict__ out_h1) {
    __shared__ float sh[256];
    int tid = threadIdx.x;
    int kp = blockIdx.y;
    int i = kp * 256 + tid;
    {   // layer-1 combine for this 256-h slice (deterministic, redundant per bx)
        float r = sigmoidf_(g_gi1[i] + g_gh1[i]);
        float z = sigmoidf_(g_gi1[i + H] + g_gh1[i + H]);
        float n = tanhf(g_gi1[i + 2 * H] + r * g_gh1[i + 2 * H]);
        float hn = (1.0f - z) * n + z * hidden[H + i];
        sh[tid] = hn;
        if (blockIdx.x == 0) out_h1[i] = hn;
    }
    __syncthreads();

    int v = blockIdx.x * 256 + tid;
    if (v < V) {
        float acc = (kp == 0) ? bd[v] : 0.f;
        const float* Wb = Wd + (size_t)(kp * 256) * V + v;
#pragma unroll 16
        for (int h = 0; h < 256; h++)
            acc += sh[h] * Wb[(size_t)h * V];
        g_logitp[kp * VP + v] = acc;
    }
}

// ---------------- K10: combine partials + softmax stats ------------------------
__global__ void k_logits_comb(float* __restrict__ out) {
    __shared__ float sred[256];
    int tid = threadIdx.x;
    int v = blockIdx.x * 256 + tid;
    float acc = -INFINITY;
    if (v < V) {
        acc = g_logitp[v] + g_logitp[VP + v] + g_logitp[2 * VP + v] + g_logitp[3 * VP + v];
        out[v] = acc;
    }
    sred[tid] = acc;
    __syncthreads();
    for (int o = 128; o > 0; o >>= 1) {
        if (tid < o) sred[tid] = fmaxf(sred[tid], sred[tid + o]);
        __syncthreads();
    }
    float bm = sred[0];
    __syncthreads();
    sred[tid] = (v < V) ? expf(acc - bm) : 0.f;
    __syncthreads();
    for (int o = 128; o > 0; o >>= 1) {
        if (tid < o) sred[tid] += sred[tid + o];
        __syncthreads();
    }
    if (tid == 0) {
        g_mpart[blockIdx.x] = bm;
        g_spart[blockIdx.x] = sred[0];
    }
}

__global__ void k_lse_combine(int nparts) {
    __shared__ float sm_[256];
    __shared__ float ss[256];
    int t = threadIdx.x;
    float m = (t < nparts) ? g_mpart[t] : -INFINITY;
    sm_[t] = m;
    __syncthreads();
    for (int o = 128; o > 0; o >>= 1) {
        if (t < o) sm_[t] = fmaxf(sm_[t], sm_[t + o]);
        __syncthreads();
    }
    float M = sm_[0];
    float s = (t < nparts) ? g_spart[t] * expf(g_mpart[t] - M) : 0.f;
    ss[t] = s;
    __syncthreads();
    for (int o = 128; o > 0; o >>= 1) {
        if (t < o) ss[t] += ss[t + o];
        __syncthreads();
    }
    if (t == 0) g_lse = M + logf(ss[0]);
}

__global__ void k_logp_final(float* __restrict__ out) {
    int v = blockIdx.x * 256 + threadIdx.x;
    if (v < V) out[v] = out[v] - g_lse;
}

// ---------------- launcher ----------------
extern "C" void kernel_launch(void* const* d_in, const int* in_sizes, int n_in,
                              void* d_out, int out_size) {
    const int*   input  = (const int*)d_in[0];
    const float* hidden = (const float*)d_in[1];
    const float* enc    = (const float*)d_in[2];
    const float* emb    = (const float*)d_in[3];
    const float* Wq     = (const float*)d_in[4];
    const float* Wk     = (const float*)d_in[5];
    const float* wv     = (const float*)d_in[6];
    const float* W_ih0  = (const float*)d_in[7];
    const float* W_hh0  = (const float*)d_in[8];
    const float* b_ih0  = (const float*)d_in[9];
    const float* b_hh0  = (const float*)d_in[10];
    const float* W_ih1  = (const float*)d_in[11];
    const float* W_hh1  = (const float*)d_in[12];
    const float* b_ih1  = (const float*)d_in[13];
    const float* b_hh1  = (const float*)d_in[14];
    const float* Wd     = (const float*)d_in[15];
    const float* bd     = (const float*)d_in[16];

    float* out = (float*)d_out;  // [0,V) logp ; [V,V+H) h0n ; [V+H,V+2H) h1n

    static int smem_set = 0;
    if (!smem_set) {
        cudaFuncSetAttribute(k_attn_gemm, cudaFuncAttributeMaxDynamicSharedMemorySize,
                             GEMM_SMEM_U32 * 4);
        smem_set = 1;
    }

    k_cvt_enc<<<L * H / 1024, 256>>>(enc);
    k_cvt_wk<<<H * H / 2 / 256, 256>>>(Wk);
    k_qw_partial<<<dim3(4, 32), 256>>>(hidden, Wq);
    k_attn_gemm<<<dim3(8, 16), 256, GEMM_SMEM_U32 * 4>>>(wv);
    k_softmax<<<1, 1024>>>();
    k_ctx_partial<<<dim3(8, 32), 128>>>(enc);
    k_build_x<<<8, 256>>>(input, emb);
    k_gru_gemv0<<<768, 256>>>(W_ih0, W_hh0, b_ih0, b_hh0, hidden);
    k_gru_gemv1<<<768, 256>>>(W_ih1, W_hh1, b_ih1, b_hh1, hidden, out + V);
    k_logits_part<<<dim3(197, 4), 256>>>(Wd, bd, hidden, out + V + H);
    k_logits_comb<<<197, 256>>>(out);
    k_lse_combine<<<1, 256>>>(197);
    k_logp_final<<<197, 256>>>(out);
}